// round 17
// baseline (speedup 1.0000x reference)
#include <cuda_runtime.h>

#define NB   64
#define N    256
#define ND   511          // number of anti-diagonals (2N-1)
#define BIGV 1e10f

// Scratch (device globals; no allocations allowed).
// Diag-major layout: X[b][d][j] = cell (i=d-j, j) of batch b.
__device__ float g_Dd[NB * ND * N];   // sheared input costs
__device__ float g_Wl[NB * ND * N];   // softmin weight w_left  per cell
__device__ float g_Wd[NB * ND * N];   // softmin weight w_diag  per cell
__device__ float g_Wu[NB * ND * N];   // softmin weight w_up    per cell
__device__ float g_Ed[NB * ND * N];   // per-batch E
__device__ float g_Es[ND * N];        // batch-mean E (diag-major)

// ---------------------------------------------------------------------------
// Shear: row-major D -> diag-major g_Dd, coalesced both ways via smem tiles.
// ---------------------------------------------------------------------------
__global__ void shear_kernel(const float* __restrict__ D) {
    __shared__ float s[32][33];
    const int b  = blockIdx.z;
    const int i0 = blockIdx.y * 32;
    const int j0 = blockIdx.x * 32;
    const int tx = threadIdx.x, ty = threadIdx.y;

    const float* Db = D + (size_t)b * N * N;
    #pragma unroll
    for (int r = ty; r < 32; r += 8)
        s[r][tx] = Db[(i0 + r) * N + j0 + tx];
    __syncthreads();

    float* out = g_Dd + (size_t)b * ND * N;
    for (int dd = ty; dd < 63; dd += 8) {
        int r = dd - tx;
        if (r >= 0 && r < 32)
            out[(i0 + j0 + dd) * N + (j0 + tx)] = s[r][tx];
    }
}

// ---------------------------------------------------------------------------
// Fused forward + backward DP. One CTA per batch, thread j = column j.
// Champion-R16 structure with both proven bit-exact chain cuts stacked:
//   (1) z-passing: smem carries z = __fdiv_rn(-R, 0.01f) (the exact op every
//       R4 consumer applied to R) -> consumers skip 2 of 3 divides  [R9-proven]
//   (2) weight expf x3 + stores deferred past __syncthreads into the next
//       step's latency shadow                                       [R16-proven]
//   (3) backward Ed store deferred past the barrier (register-held value).
// ---------------------------------------------------------------------------
__global__ __launch_bounds__(256) void dp_kernel() {
    __shared__ float sb[10][N];

    const int b = blockIdx.x;
    const size_t base = (size_t)b * ND * N;
    const float* __restrict__ Dd = g_Dd + base;
    float* __restrict__ Wl = g_Wl + base;
    float* __restrict__ Wd = g_Wd + base;
    float* __restrict__ Wu = g_Wu + base;
    float* __restrict__ Ed = g_Ed + base;

    const int j = threadIdx.x;
    const bool jgt0 = (j > 0);
    const bool jlt  = (j < N - 1);
    const float ZBIG  = __fdiv_rn(-BIGV, 0.01f);
    const float ZZERO = __fdiv_rn(-0.0f, 0.01f);

    // ---------------- forward ----------------
    {
        float *zcur = sb[0], *zp1 = sb[1], *zp2 = sb[2];
        float th0 = Dd[j];                              // depth-2 prefetch
        float th1 = Dd[N + j];
        // pending-weight registers (deferred past the barrier)
        bool  p_act = false;
        int   p_d   = 0;
        float p_zl = 0.f, p_zd = 0.f, p_zu = 0.f, p_lse = 0.f;

        for (int d = 0; d < ND; ++d) {
            float thN = 0.0f;
            if (d + 2 < ND) thN = Dd[(size_t)(d + 2) * N + j];

            // flush previous step's weights (off the barrier-arrival path)
            if (p_act) {
                const size_t o = (size_t)p_d * N + j;
                Wl[o] = expf(__fsub_rn(p_zl, p_lse));
                Wd[o] = expf(__fsub_rn(p_zd, p_lse));
                Wu[o] = expf(__fsub_rn(p_zu, p_lse));
            }

            const int i = d - j;
            const bool act = ((unsigned)i < (unsigned)N);
            if (act) {
                const float zl = jgt0    ? zp1[j - 1] : ZBIG;       // z(i, j-1)
                const float zu = (i > 0) ? zp1[j]     : ZBIG;       // z(i-1, j)
                float zd;                                           // z(i-1, j-1)
                if (i > 0 && jgt0)       zd = zp2[j - 1];
                else                     zd = (i == 0 && j == 0) ? ZZERO : ZBIG;

                const float zmax = fmaxf(fmaxf(zl, zd), zu);
                const float el = expf(__fsub_rn(zl, zmax));
                const float ed = expf(__fsub_rn(zd, zmax));
                const float eu = expf(__fsub_rn(zu, zmax));
                const float ssum = __fadd_rn(__fadd_rn(el, ed), eu);
                const float lse  = __fadd_rn(logf(ssum), zmax);
                const float R    = __fadd_rn(th0, __fmul_rn(-0.01f, lse));
                zcur[j] = __fdiv_rn(-R, 0.01f);

                p_zl = zl; p_zd = zd; p_zu = zu; p_lse = lse; p_d = d;
            }
            p_act = act;
            __syncthreads();
            th0 = th1; th1 = thN;
            float* t = zp2; zp2 = zp1; zp1 = zcur; zcur = t;
        }
        // epilogue: flush last pending weights
        if (p_act) {
            const size_t o = (size_t)p_d * N + j;
            Wl[o] = expf(__fsub_rn(p_zl, p_lse));
            Wd[o] = expf(__fsub_rn(p_zd, p_lse));
            Wu[o] = expf(__fsub_rn(p_zu, p_lse));
        }
    }
    __syncthreads();

    // ---------------- backward (R4 values; deferred Ed store) ----------------
    {
        float *ecur = sb[0], *ep1 = sb[1], *ep2 = sb[2];
        float *qlc  = sb[3], *qlp = sb[4];                  // w_left  (cur, d+1)
        float *quc  = sb[5], *qup = sb[6];                  // w_up    (cur, d+1)
        float *qdc  = sb[7], *qdp1 = sb[8], *qdp2 = sb[9];  // w_diag  (cur, d+1, d+2)

        // depth-2 pipeline: slot0 = W(d), slot1 = W(d-1)
        float wl0 = Wl[(size_t)(ND - 1) * N + j];
        float wd0 = Wd[(size_t)(ND - 1) * N + j];
        float wu0 = Wu[(size_t)(ND - 1) * N + j];
        float wl1 = Wl[(size_t)(ND - 2) * N + j];
        float wd1p = Wd[(size_t)(ND - 2) * N + j];
        float wu1p = Wu[(size_t)(ND - 2) * N + j];

        // pending Ed store (deferred past the barrier)
        bool  p_act = false;
        int   p_d   = 0;
        float p_e   = 0.f;

        for (int d = ND - 1; d >= 0; --d) {
            float wlN = 0.0f, wdN = 0.0f, wuN = 0.0f;
            if (d - 2 >= 0) {
                wlN = Wl[(size_t)(d - 2) * N + j];
                wdN = Wd[(size_t)(d - 2) * N + j];
                wuN = Wu[(size_t)(d - 2) * N + j];
            }

            // flush previous step's Ed store (off the barrier-arrival path)
            if (p_act) Ed[(size_t)p_d * N + j] = p_e;

            const int i = d - j;
            const bool act = ((unsigned)i < (unsigned)N);
            if (act) {
                float e;
                if (i == N - 1 && j == N - 1) {
                    e = 1.0f;
                } else {
                    float t0 = 0.0f, t1 = 0.0f, t2 = 0.0f;
                    if (jlt)                       // from (i, j+1)  @ diag d+1
                        t0 = __fmul_rn(qlp[j + 1], ep1[j + 1]);
                    if (i < N - 1) {
                        if (jlt)                   // from (i+1,j+1) @ diag d+2
                            t1 = __fmul_rn(qdp2[j + 1], ep2[j + 1]);
                        t2 = __fmul_rn(qup[j], ep1[j]);   // from (i+1, j) @ d+1
                    }
                    e = __fadd_rn(__fadd_rn(t0, t1), t2);
                }
                ecur[j] = e;
                qlc[j] = wl0;
                quc[j] = wu0;
                qdc[j] = wd0;
                p_e = e; p_d = d;
            }
            p_act = act;
            __syncthreads();
            wl0 = wl1;  wd0 = wd1p; wu0 = wu1p;
            wl1 = wlN;  wd1p = wdN; wu1p = wuN;
            float* t;
            t = ep2;  ep2  = ep1;  ep1 = ecur; ecur = t;
            t = qlp;  qlp  = qlc;  qlc = t;
            t = qup;  qup  = quc;  quc = t;
            t = qdp2; qdp2 = qdp1; qdp1 = qdc; qdc = t;
        }
        // epilogue: flush last pending Ed store
        if (p_act) Ed[(size_t)p_d * N + j] = p_e;
    }
}

// ---------------------------------------------------------------------------
__global__ void reduce_kernel() {
    const int idx = blockIdx.x * blockDim.x + threadIdx.x;   // < ND*N
    float s = 0.0f;
    #pragma unroll 4
    for (int b = 0; b < NB; ++b) s += g_Ed[(size_t)b * ND * N + idx];
    g_Es[idx] = s * (1.0f / NB);
}

__global__ void gather_kernel(float* __restrict__ out) {
    const int idx = blockIdx.x * blockDim.x + threadIdx.x;   // < N*N
    const int i = idx >> 8, j = idx & (N - 1);
    out[idx] = g_Es[(i + j) * N + j];
}

// ---------------------------------------------------------------------------
extern "C" void kernel_launch(void* const* d_in, const int* in_sizes, int n_in,
                              void* d_out, int out_size) {
    const float* D = (const float*)d_in[0];
    float* out = (float*)d_out;

    shear_kernel<<<dim3(8, 8, NB), dim3(32, 8)>>>(D);
    dp_kernel<<<NB, 256>>>();
    reduce_kernel<<<ND, 256>>>();
    gather_kernel<<<(N * N) / 256, 256>>>(out);
}